// round 4
// baseline (speedup 1.0000x reference)
#include <cuda_runtime.h>

#define N_NODES 100000
#define N_EDGES 1000000
#define NB 98  // ceil(N_NODES/1024)

// ---------------- device scratch (no allocations allowed) ----------------
__device__ int   g_is64;
__device__ int   g_deg[N_NODES];
__device__ int   g_rowstart[N_NODES + 1];
__device__ int   g_fill[N_NODES];
__device__ int   g_col[N_EDGES];
__device__ float g_mean[N_NODES * 64];
__device__ float g_p[N_NODES * 2];   // h @ Wl2^T  (to be mean-aggregated)
__device__ float g_q[N_NODES * 2];   // h @ Wr2^T + b2 (local term)

// ---------------- init: zero degrees + dtype sniff ----------------
__global__ void k_init(const int* __restrict__ ei32) {
    int i = blockIdx.x * blockDim.x + threadIdx.x;
    if (i < N_NODES) g_deg[i] = 0;
    if (i == 0) {
        // int64 nonneg < 2^31 => every odd int32 word is 0
        int any = 0;
        for (int s = 1; s < 64; s += 2) any |= ei32[s];
        g_is64 = (any == 0) ? 1 : 0;
    }
}

// ---------------- CSR build ----------------
// count: 4 edges per thread (vectorized int4 on int32 path)
__global__ void k_count(const void* __restrict__ ei) {
    int e4 = blockIdx.x * blockDim.x + threadIdx.x;
    if (e4 >= N_EDGES / 4) return;
    int d0, d1, d2, d3;
    if (!g_is64) {
        const int4* p = (const int4*)((const int*)ei + N_EDGES);
        int4 v = p[e4];
        d0 = v.x; d1 = v.y; d2 = v.z; d3 = v.w;
    } else {
        const long long* q = (const long long*)ei + N_EDGES + (long long)e4 * 4;
        d0 = (int)q[0]; d1 = (int)q[1]; d2 = (int)q[2]; d3 = (int)q[3];
    }
    if ((unsigned)d0 < (unsigned)N_NODES) atomicAdd(&g_deg[d0], 1);
    if ((unsigned)d1 < (unsigned)N_NODES) atomicAdd(&g_deg[d1], 1);
    if ((unsigned)d2 < (unsigned)N_NODES) atomicAdd(&g_deg[d2], 1);
    if ((unsigned)d3 < (unsigned)N_NODES) atomicAdd(&g_deg[d3], 1);
}

// scanrow: one kernel replaces blocksum+scanbase+rowstart.
// Block b sums deg[0 .. b*1024) itself (triangular total = ~19MB L2 reads),
// then scans its own 1024 degrees and writes rowstart/fill.
__global__ void k_scanrow() {
    __shared__ int red[256];
    int b = blockIdx.x, t = threadIdx.x;

    // 1) base = sum of all preceding blocks' degrees
    int limit4 = (b * 1024) >> 2;          // multiple of 256
    const int4* d4 = (const int4*)g_deg;
    int sum = 0;
    for (int i = t; i < limit4; i += 256) {
        int4 v = d4[i];
        sum += v.x + v.y + v.z + v.w;
    }
    red[t] = sum; __syncthreads();
    for (int o = 128; o > 0; o >>= 1) {
        if (t < o) red[t] += red[t + o];
        __syncthreads();
    }
    int blockbase = red[0];
    __syncthreads();

    // 2) scan own 1024 degrees (4 per thread)
    int base_node = b * 1024 + t * 4;
    int v[4]; int tot = 0;
#pragma unroll
    for (int i = 0; i < 4; i++) {
        int nd = base_node + i;
        v[i] = (nd < N_NODES) ? g_deg[nd] : 0;
        tot += v[i];
    }
    red[t] = tot; __syncthreads();
    for (int o = 1; o < 256; o <<= 1) {
        int u = (t >= o) ? red[t - o] : 0;
        __syncthreads();
        red[t] += u;
        __syncthreads();
    }
    int run = blockbase + red[t] - tot;   // exclusive within block + base
#pragma unroll
    for (int i = 0; i < 4; i++) {
        int nd = base_node + i;
        if (nd < N_NODES) {
            g_rowstart[nd] = run;
            g_fill[nd] = run;
            run += v[i];
            if (nd == N_NODES - 1) g_rowstart[N_NODES] = run;
        }
    }
}

// fill: 4 edges per thread (vectorized int4 on int32 path)
__global__ void k_fill(const void* __restrict__ ei) {
    int e4 = blockIdx.x * blockDim.x + threadIdx.x;
    if (e4 >= N_EDGES / 4) return;
    int s0, s1, s2, s3, d0, d1, d2, d3;
    if (!g_is64) {
        const int4* ps = (const int4*)((const int*)ei);
        const int4* pd = (const int4*)((const int*)ei + N_EDGES);
        int4 vs = ps[e4]; int4 vd = pd[e4];
        s0 = vs.x; s1 = vs.y; s2 = vs.z; s3 = vs.w;
        d0 = vd.x; d1 = vd.y; d2 = vd.z; d3 = vd.w;
    } else {
        const long long* qs = (const long long*)ei + (long long)e4 * 4;
        const long long* qd = (const long long*)ei + N_EDGES + (long long)e4 * 4;
        s0 = (int)qs[0]; s1 = (int)qs[1]; s2 = (int)qs[2]; s3 = (int)qs[3];
        d0 = (int)qd[0]; d1 = (int)qd[1]; d2 = (int)qd[2]; d3 = (int)qd[3];
    }
#define FILL1(ss, dd) \
    if ((unsigned)(dd) < (unsigned)N_NODES && (unsigned)(ss) < (unsigned)N_NODES) { \
        int pos = atomicAdd(&g_fill[dd], 1); \
        if ((unsigned)pos < (unsigned)N_EDGES) g_col[pos] = (ss); \
    }
    FILL1(s0, d0) FILL1(s1, d1) FILL1(s2, d2) FILL1(s3, d3)
#undef FILL1
}

// ---------------- layer 1: mean aggregation (warp per node, float2 lanes) ----------------
__global__ void k_gather_mean(const float* __restrict__ x) {
    int w = (blockIdx.x * blockDim.x + threadIdx.x) >> 5;
    if (w >= N_NODES) return;
    int lane = threadIdx.x & 31;
    int s = g_rowstart[w], e = g_rowstart[w + 1];
    const float2* x2 = (const float2*)x;
    float ax0 = 0.f, ay0 = 0.f, ax1 = 0.f, ay1 = 0.f;
    float ax2 = 0.f, ay2 = 0.f, ax3 = 0.f, ay3 = 0.f;
    int j = s;
    int nn = e - ((e - s) & 3);
    for (; j < nn; j += 4) {
        int c0 = g_col[j], c1 = g_col[j + 1], c2 = g_col[j + 2], c3 = g_col[j + 3];
        float2 v0 = x2[c0 * 32 + lane];
        float2 v1 = x2[c1 * 32 + lane];
        float2 v2 = x2[c2 * 32 + lane];
        float2 v3 = x2[c3 * 32 + lane];
        ax0 += v0.x; ay0 += v0.y;
        ax1 += v1.x; ay1 += v1.y;
        ax2 += v2.x; ay2 += v2.y;
        ax3 += v3.x; ay3 += v3.y;
    }
    for (; j < e; j++) {
        int c = g_col[j];
        float2 v = x2[c * 32 + lane];
        ax0 += v.x; ay0 += v.y;
    }
    float inv = 1.f / (float)max(e - s, 1);
    float2 r;
    r.x = ((ax0 + ax1) + (ax2 + ax3)) * inv;
    r.y = ((ay0 + ay1) + (ay2 + ay3)) * inv;
    ((float2*)g_mean)[w * 32 + lane] = r;
}

// ---------------- layer 1 GEMM (outer-product tiled, packed f32x2) ----------------
// h = relu([mean||x] @ [Wl1||Wr1]^T + b1);  p = h@Wl2^T;  q = h@Wr2^T + b2
#define KC 16
#define WPAD 68
#define APAD 132

__device__ __forceinline__ unsigned long long pack2(float v) {
    unsigned long long r;
    asm("mov.b64 %0, {%1, %1};" : "=l"(r) : "f"(v));
    return r;
}
__device__ __forceinline__ void fma2(unsigned long long& acc,
                                     unsigned long long a, unsigned long long w) {
    asm("fma.rn.f32x2 %0, %1, %2, %0;" : "+l"(acc) : "l"(a), "l"(w));
}

__global__ __launch_bounds__(256) void k_layer1(
    const float* __restrict__ x,
    const float* __restrict__ Wl1, const float* __restrict__ Wr1,
    const float* __restrict__ b1,
    const float* __restrict__ Wl2, const float* __restrict__ Wr2,
    const float* __restrict__ b2)
{
    __shared__ __align__(16) float sWt[128][WPAD];  // [k][j] transposed
    __shared__ __align__(16) float sAs[KC][APAD];   // [k][n] transposed chunk
    __shared__ float sL2[128], sR2[128], sB1[64];

    int t = threadIdx.x;
    for (int i = t; i < 64 * 64; i += 256) {
        int j = i >> 6, k = i & 63;
        sWt[k][j]      = Wl1[i];
        sWt[k + 64][j] = Wr1[i];
    }
    if (t < 128) { sL2[t] = Wl2[t]; sR2[t] = Wr2[t]; }
    if (t < 64)  sB1[t] = b1[t];

    int tn = t >> 3;          // 0..31 : node group
    int tj = t & 7;           // 0..7  : out group
    int nodeBase = blockIdx.x * 128;

    unsigned long long acc[4][4];
#pragma unroll
    for (int i = 0; i < 4; i++)
#pragma unroll
        for (int jp = 0; jp < 4; jp++) acc[i][jp] = 0ull;

    int r  = t >> 1;
    int kq = (t & 1) * 2;
    int nL = nodeBase + r; if (nL >= N_NODES) nL = N_NODES - 1;

    for (int ch = 0; ch < 8; ch++) {
        __syncthreads();
        {
            const float* src = (ch < 4) ? (g_mean + (size_t)nL * 64 + ch * 16)
                                        : (x      + (size_t)nL * 64 + (ch - 4) * 16);
            const float4* s4 = (const float4*)src;
#pragma unroll
            for (int q = 0; q < 2; q++) {
                float4 v = s4[kq + q];
                int kk = (kq + q) * 4;
                sAs[kk][r] = v.x; sAs[kk + 1][r] = v.y;
                sAs[kk + 2][r] = v.z; sAs[kk + 3][r] = v.w;
            }
        }
        __syncthreads();
        int kbase = ch * KC;
#pragma unroll
        for (int k = 0; k < KC; k++) {
            float4 a4 = *(const float4*)&sAs[k][tn * 4];
            unsigned long long a2[4];
            a2[0] = pack2(a4.x); a2[1] = pack2(a4.y);
            a2[2] = pack2(a4.z); a2[3] = pack2(a4.w);
            const float* wrow = &sWt[kbase + k][tj * 8];
            unsigned long long w2[4];
            {
                float4 w0 = *(const float4*)(wrow);
                float4 w1 = *(const float4*)(wrow + 4);
                w2[0] = *(unsigned long long*)&w0.x;
                w2[1] = *(unsigned long long*)&w0.z;
                w2[2] = *(unsigned long long*)&w1.x;
                w2[3] = *(unsigned long long*)&w1.z;
            }
#pragma unroll
            for (int i = 0; i < 4; i++)
#pragma unroll
                for (int jp = 0; jp < 4; jp++)
                    fma2(acc[i][jp], a2[i], w2[jp]);
        }
    }

    float bq0 = b2[0], bq1 = b2[1];
#pragma unroll
    for (int i = 0; i < 4; i++) {
        float p0 = 0.f, p1 = 0.f, q0 = 0.f, q1 = 0.f;
#pragma unroll
        for (int jp = 0; jp < 4; jp++) {
            float lo, hi;
            asm("mov.b64 {%0, %1}, %2;" : "=f"(lo), "=f"(hi) : "l"(acc[i][jp]));
            int j = tj * 8 + jp * 2;
            float h0 = fmaxf(lo + sB1[j], 0.f);
            float h1 = fmaxf(hi + sB1[j + 1], 0.f);
            p0 += h0 * sL2[j]      + h1 * sL2[j + 1];
            p1 += h0 * sL2[64 + j] + h1 * sL2[64 + j + 1];
            q0 += h0 * sR2[j]      + h1 * sR2[j + 1];
            q1 += h0 * sR2[64 + j] + h1 * sR2[64 + j + 1];
        }
#pragma unroll
        for (int o = 4; o > 0; o >>= 1) {
            p0 += __shfl_xor_sync(0xFFFFFFFFu, p0, o);
            p1 += __shfl_xor_sync(0xFFFFFFFFu, p1, o);
            q0 += __shfl_xor_sync(0xFFFFFFFFu, q0, o);
            q1 += __shfl_xor_sync(0xFFFFFFFFu, q1, o);
        }
        if (tj == 0) {
            int n = nodeBase + tn * 4 + i;
            if (n < N_NODES) {
                g_p[n * 2]     = p0;
                g_p[n * 2 + 1] = p1;
                g_q[n * 2]     = q0 + bq0;
                g_q[n * 2 + 1] = q1 + bq1;
            }
        }
    }
}

// ---------------- layer 2: mean-aggregate p (2 floats/edge) + local q ----------------
__global__ void k_layer2_out(float* __restrict__ out) {
    int w = (blockIdx.x * blockDim.x + threadIdx.x) >> 5;
    if (w >= N_NODES) return;
    int lane = threadIdx.x & 31;
    int s = g_rowstart[w], e = g_rowstart[w + 1];
    float a0 = 0.f, a1 = 0.f;
    for (int j = s + lane; j < e; j += 32) {
        int src = g_col[j];
        float2 pv = *(const float2*)(g_p + src * 2);
        a0 += pv.x; a1 += pv.y;
    }
#pragma unroll
    for (int o = 16; o > 0; o >>= 1) {
        a0 += __shfl_xor_sync(0xFFFFFFFFu, a0, o);
        a1 += __shfl_xor_sync(0xFFFFFFFFu, a1, o);
    }
    if (lane == 0) {
        float inv = 1.f / (float)max(e - s, 1);
        out[w * 2]     = a0 * inv + g_q[w * 2];
        out[w * 2 + 1] = a1 * inv + g_q[w * 2 + 1];
    }
}

// ---------------- launch ----------------
extern "C" void kernel_launch(void* const* d_in, const int* in_sizes, int n_in,
                              void* d_out, int out_size)
{
    const float* x   = (const float*)d_in[0];
    const void*  ei  = d_in[1];                 // int32 or int64, sniffed on device
    const float* Wl1 = (const float*)d_in[2];
    const float* Wr1 = (const float*)d_in[3];
    const float* b1  = (const float*)d_in[4];
    const float* Wl2 = (const float*)d_in[5];
    const float* Wr2 = (const float*)d_in[6];
    const float* b2  = (const float*)d_in[7];
    float* out = (float*)d_out;

    k_init<<<(N_NODES + 255) / 256, 256>>>((const int*)ei);
    k_count<<<(N_EDGES / 4 + 255) / 256, 256>>>(ei);
    k_scanrow<<<NB, 256>>>();
    k_fill<<<(N_EDGES / 4 + 255) / 256, 256>>>(ei);

    int warps_grid = (N_NODES * 32 + 255) / 256;
    k_gather_mean<<<warps_grid, 256>>>(x);
    k_layer1<<<(N_NODES + 127) / 128, 256>>>(x, Wl1, Wr1, b1, Wl2, Wr2, b2);
    k_layer2_out<<<warps_grid, 256>>>(out);
}